// round 6
// baseline (speedup 1.0000x reference)
#include <cuda_runtime.h>
#include <cuda_bf16.h>

// Problem constants (fixed by the reference: pc (4,4096,3), mask (4,4096,30))
#define BQ_B 4
#define BQ_N 4096
#define BQ_C 30
#define BQ_K 16
#define BQ_R2 0.04f

#define WARPS_PER_BLOCK 8
#define NUM_QUERIES (BQ_B * BQ_N)                       // 16384
#define NUM_BLOCKS (NUM_QUERIES / WARPS_PER_BLOCK)      // 2048

__device__ float4  g_pts[NUM_QUERIES];   // (x, y, z, x^2+y^2+z^2) per point
__device__ float   g_partials[NUM_BLOCKS];
__device__ unsigned g_ticket = 0;        // reset by the last block each launch

// ---- Prep: pack pc into float4 with precomputed squared norm ----
__global__ __launch_bounds__(256)
void ballq_prep_kernel(const float* __restrict__ pc) {
    const int i = blockIdx.x * 256 + threadIdx.x;        // 0..16383
    const float x = pc[i * 3 + 0];
    const float y = pc[i * 3 + 1];
    const float z = pc[i * 3 + 2];
    g_pts[i] = make_float4(x, y, z, x * x + y * y + z * z);
}

__global__ __launch_bounds__(WARPS_PER_BLOCK * 32)
void ballq_loss_kernel(const float* __restrict__ mask,
                       float* __restrict__ out) {
    const int warp = threadIdx.x >> 5;
    const int lane = threadIdx.x & 31;
    const int q = blockIdx.x * WARPS_PER_BLOCK + warp;   // query id, 0..16383
    const int b = q >> 12;                               // q / 4096
    const int n = q & (BQ_N - 1);                        // q % 4096

    const float4* __restrict__ pts = g_pts + b * BQ_N;

    // Query point: one broadcast float4 load
    const float4 qp = pts[n];
    const float qx = qp.x, qy = qp.y, qz = qp.z, qsq = qp.w;

    const unsigned lanemask_lt = (1u << lane) - 1u;

    __shared__ int sidx[WARPS_PER_BLOCK][BQ_K];

    // ---- Ball-query scan: first K indices (in index order) with d2 < R2 ----
    // 128 candidates/iter, all 4 LDG.128 issued before any ballot.
    // d2 = qsq + msq - 2*dot matches the reference's algebraic form so
    // boundary rounding errors correlate with the reference.
    int cnt = 0;  // uniform across the warp (may exceed K transiently)
    for (int base = 0; base < BQ_N && cnt < BQ_K; base += 128) {
        float d2[4];
#pragma unroll
        for (int j = 0; j < 4; j++) {
            const float4 p = pts[base + j * 32 + lane];  // N % 128 == 0
            const float dot = qx * p.x + qy * p.y + qz * p.z;
            d2[j] = qsq + p.w - 2.0f * dot;
        }
#pragma unroll
        for (int j = 0; j < 4; j++) {
            if (cnt < BQ_K) {                            // uniform predicate
                const bool hit = d2[j] < BQ_R2;
                const unsigned bal = __ballot_sync(0xffffffffu, hit);
                // Rank-based parallel write: no serial bit-peel
                const int slot = cnt + __popc(bal & lanemask_lt);
                if (hit && slot < BQ_K)
                    sidx[warp][slot] = base + j * 32 + lane;
                cnt += __popc(bal);
            }
        }
    }
    __syncwarp();
    // Pad remaining slots with the first found index (cnt >= 1 always: self hit)
    if (lane == 0) {
        const int f = sidx[warp][0];
        for (int j = (cnt < BQ_K ? cnt : BQ_K); j < BQ_K; j++) sidx[warp][j] = f;
    }
    __syncwarp();

    // ---- Loss: lane c handles channel c (c < 30); neighbor rows coalesced ----
    float acc = 0.0f;
    if (lane < BQ_C) {
        const float* __restrict__ mb = mask + (size_t)b * BQ_N * BQ_C;
        const float mq = mb[n * BQ_C + lane];
#pragma unroll
        for (int j = 0; j < BQ_K; j++) {
            const int id = sidx[warp][j];
            acc += fabsf(mq - mb[id * BQ_C + lane]);
        }
    }
    // Warp reduce (lanes 30,31 contribute 0)
#pragma unroll
    for (int off = 16; off; off >>= 1)
        acc += __shfl_down_sync(0xffffffffu, acc, off);

    __shared__ float wl[WARPS_PER_BLOCK];
    if (lane == 0) wl[warp] = acc;
    __syncthreads();

    // Per-block partial in fixed order (no float atomics -> deterministic)
    __shared__ bool is_last;
    if (threadIdx.x == 0) {
        float s = 0.0f;
#pragma unroll
        for (int w = 0; w < WARPS_PER_BLOCK; w++) s += wl[w];
        g_partials[blockIdx.x] = s;
        __threadfence();                                  // publish partial
        unsigned t = atomicAdd(&g_ticket, 1u);            // int ticket only
        is_last = (t == NUM_BLOCKS - 1);
    }
    __syncthreads();

    // ---- Fused final reduction: last block, fixed order, deterministic ----
    if (is_last) {
        __shared__ float sh[256];
        float s = 0.0f;
        for (int i = threadIdx.x; i < NUM_BLOCKS; i += 256)
            s += g_partials[i];
        sh[threadIdx.x] = s;
        __syncthreads();
#pragma unroll
        for (int off = 128; off; off >>= 1) {
            if (threadIdx.x < off) sh[threadIdx.x] += sh[threadIdx.x + off];
            __syncthreads();
        }
        if (threadIdx.x == 0) {
            out[0] = sh[0] * (1.0f / ((float)BQ_K * (float)NUM_QUERIES));
            g_ticket = 0;                                 // reset for next replay
        }
    }
}

extern "C" void kernel_launch(void* const* d_in, const int* in_sizes, int n_in,
                              void* d_out, int out_size) {
    const float* pc   = (const float*)d_in[0];   // (4, 4096, 3) float32
    const float* mask = (const float*)d_in[1];   // (4, 4096, 30) float32
    float* out = (float*)d_out;                  // scalar float32

    ballq_prep_kernel<<<NUM_QUERIES / 256, 256>>>(pc);
    ballq_loss_kernel<<<NUM_BLOCKS, WARPS_PER_BLOCK * 32>>>(mask, out);
}

// round 7
// speedup vs baseline: 1.0428x; 1.0428x over previous
#include <cuda_runtime.h>
#include <cuda_bf16.h>

// Problem constants (fixed by the reference: pc (4,4096,3), mask (4,4096,30))
#define BQ_B 4
#define BQ_N 4096
#define BQ_C 30
#define BQ_K 16
#define BQ_R2 0.04f

#define WARPS_PER_BLOCK 8
#define NUM_QUERIES (BQ_B * BQ_N)                       // 16384
#define NUM_BLOCKS (NUM_QUERIES / WARPS_PER_BLOCK)      // 2048

__device__ float    g_partials[NUM_BLOCKS];
__device__ unsigned g_ticket = 0;   // reset by the last block each launch

__global__ __launch_bounds__(WARPS_PER_BLOCK * 32)
void ballq_loss_kernel(const float* __restrict__ pc,
                       const float* __restrict__ mask,
                       float* __restrict__ out) {
    const int warp = threadIdx.x >> 5;
    const int lane = threadIdx.x & 31;
    const int q = blockIdx.x * WARPS_PER_BLOCK + warp;   // query id, 0..16383
    const int b = q >> 12;                               // q / 4096
    const int n = q & (BQ_N - 1);                        // q % 4096

    const float* __restrict__ pcb = pc + (size_t)b * BQ_N * 3;

    // Query point (broadcast load, same address across warp)
    const float qx = pcb[n * 3 + 0];
    const float qy = pcb[n * 3 + 1];
    const float qz = pcb[n * 3 + 2];
    const float qsq = qx * qx + qy * qy + qz * qz;

    __shared__ int sidx[WARPS_PER_BLOCK][BQ_K];

    // Lane-base pointer: candidate m = base + j*32 + lane lives at
    // pl[base*3 + j*96 + {0,1,2}] -> LDG with immediate offsets, one pointer.
    const float* __restrict__ pl = pcb + lane * 3;

    // ---- Ball-query scan: first K indices (index order) with d2 < R2 ----
    // 2-stage software pipeline: next 128-block's 12 loads are issued before
    // the current block's ballots are peeled, hiding L1 latency.
    // d2 uses the reference's algebraic form (qsq + msq - 2*dot) so boundary
    // rounding errors correlate with the reference.
    float cx[4], cy[4], cz[4];
#pragma unroll
    for (int j = 0; j < 4; j++) {
        cx[j] = pl[j * 96 + 0];
        cy[j] = pl[j * 96 + 1];
        cz[j] = pl[j * 96 + 2];
    }

    int cnt = 0;  // uniform across the warp; never exceeds BQ_K
    for (int base = 0; base < BQ_N && cnt < BQ_K; base += 128) {
        // Prefetch next block (harmless re-read of current block on last iter)
        const int nbase = (base + 128 < BQ_N) ? (base + 128) : base;
        const float* __restrict__ pn = pl + nbase * 3;
        float nx[4], ny[4], nz[4];
#pragma unroll
        for (int j = 0; j < 4; j++) {
            nx[j] = pn[j * 96 + 0];
            ny[j] = pn[j * 96 + 1];
            nz[j] = pn[j * 96 + 2];
        }

        // Compute d2 + 4 unconditional ballots (no cnt-dependent branches)
        unsigned bal[4];
#pragma unroll
        for (int j = 0; j < 4; j++) {
            const float msq = cx[j] * cx[j] + cy[j] * cy[j] + cz[j] * cz[j];
            const float dot = qx * cx[j] + qy * cy[j] + qz * cz[j];
            const float d2  = qsq + msq - 2.0f * dot;
            bal[j] = __ballot_sync(0xffffffffu, d2 < BQ_R2);
        }

        // Merged 128-bit peel, lowest index first (order-preserving)
        unsigned long long w  = (unsigned long long)bal[0] |
                                ((unsigned long long)bal[1] << 32);
        const unsigned long long hi = (unsigned long long)bal[2] |
                                ((unsigned long long)bal[3] << 32);
        int off = 0;
        while (cnt < BQ_K) {
            if (w == 0ull) {
                if (off == 64) break;
                w = hi; off = 64;
                continue;
            }
            const int l = __ffsll(w) - 1;
            if (lane == 0) sidx[warp][cnt] = base + off + l;
            cnt++;
            w &= w - 1ull;
        }

        // Rotate pipeline buffers
#pragma unroll
        for (int j = 0; j < 4; j++) { cx[j] = nx[j]; cy[j] = ny[j]; cz[j] = nz[j]; }
    }
    // Pad remaining slots with the first found index (cnt >= 1 always: self hit)
    if (lane == 0) {
        const int f = sidx[warp][0];
        for (int j = cnt; j < BQ_K; j++) sidx[warp][j] = f;
    }
    __syncwarp();

    // ---- Loss: lane c handles channel c (c < 30); neighbor rows coalesced ----
    float acc = 0.0f;
    if (lane < BQ_C) {
        const float* __restrict__ mb = mask + (size_t)b * BQ_N * BQ_C;
        const float mq = mb[n * BQ_C + lane];
#pragma unroll
        for (int j = 0; j < BQ_K; j++) {
            const int id = sidx[warp][j];
            acc += fabsf(mq - mb[id * BQ_C + lane]);
        }
    }
    // Warp reduce (lanes 30,31 contribute 0)
#pragma unroll
    for (int off = 16; off; off >>= 1)
        acc += __shfl_down_sync(0xffffffffu, acc, off);

    __shared__ float wl[WARPS_PER_BLOCK];
    if (lane == 0) wl[warp] = acc;
    __syncthreads();

    // Per-block partial in fixed order (no float atomics -> deterministic)
    __shared__ bool is_last;
    if (threadIdx.x == 0) {
        float s = 0.0f;
#pragma unroll
        for (int w2 = 0; w2 < WARPS_PER_BLOCK; w2++) s += wl[w2];
        g_partials[blockIdx.x] = s;
        __threadfence();                                  // publish partial
        unsigned t = atomicAdd(&g_ticket, 1u);            // int ticket only
        is_last = (t == NUM_BLOCKS - 1);
    }
    __syncthreads();

    // ---- Fused final reduction: last block, fixed order, deterministic ----
    if (is_last) {
        __shared__ float sh[256];
        float s = 0.0f;
        for (int i = threadIdx.x; i < NUM_BLOCKS; i += 256)
            s += g_partials[i];
        sh[threadIdx.x] = s;
        __syncthreads();
#pragma unroll
        for (int off = 128; off; off >>= 1) {
            if (threadIdx.x < off) sh[threadIdx.x] += sh[threadIdx.x + off];
            __syncthreads();
        }
        if (threadIdx.x == 0) {
            out[0] = sh[0] * (1.0f / ((float)BQ_K * (float)NUM_QUERIES));
            g_ticket = 0;                                 // reset for next replay
        }
    }
}

extern "C" void kernel_launch(void* const* d_in, const int* in_sizes, int n_in,
                              void* d_out, int out_size) {
    const float* pc   = (const float*)d_in[0];   // (4, 4096, 3) float32
    const float* mask = (const float*)d_in[1];   // (4, 4096, 30) float32
    float* out = (float*)d_out;                  // scalar float32

    ballq_loss_kernel<<<NUM_BLOCKS, WARPS_PER_BLOCK * 32>>>(pc, mask, out);
}